// round 1
// baseline (speedup 1.0000x reference)
#include <cuda_runtime.h>
#include <math.h>

#define NB    38          // B*K = 2*19
#define MPTS  1024
#define NP    128         // NPOINT
#define NS    128         // NSAMPLE
#define CIN   256
#define R2C   0.0225f

// ---------------- scratch (__device__ globals, no allocation) ----------------
__device__ float g_x[NB * MPTS * 3];
__device__ int   g_idx[NB * NP * NS];
__device__ float g_Ffs[NB * 128 * MPTS];     // alpha1 * (W1f @ f)
__device__ float g_W1ft[CIN * 128];          // [c][o], alpha1-folded
__device__ float g_Wg[128 * 3];              // alpha1 * W1 xyz part
__device__ float g_beta1[128];
__device__ float g_Wt2[128 * 128];           // [c][o] alpha-folded
__device__ float g_bt2[128];
__device__ float g_Wt3[128 * 128];
__device__ float g_bt3[128];
__device__ float g_Wc1[128 * 128];
__device__ float g_bc1[128];
__device__ float g_Wc2[128 * 128];
__device__ float g_bc2[128];

// ---------------- prep: fold BN into transposed weights ----------------
__global__ void prep_kernel(const float* m1_w, const float* m1_b, const float* m1_g, const float* m1_be,
                            const float* m2_w, const float* m2_b, const float* m2_g, const float* m2_be,
                            const float* m3_w, const float* m3_b, const float* m3_g, const float* m3_be,
                            const float* c1_w, const float* c1_b, const float* c1_g, const float* c1_be,
                            const float* c2_w, const float* c2_b, const float* c2_g, const float* c2_be) {
    const float s = sqrtf(1.0f + 1e-5f);
    int t = blockIdx.x * blockDim.x + threadIdx.x;
    int stride = gridDim.x * blockDim.x;
    for (int i = t; i < CIN * 128; i += stride) {
        int c = i >> 7, o = i & 127;
        g_W1ft[i] = (m1_g[o] / s) * m1_w[o * 259 + 3 + c];
    }
    for (int i = t; i < 128 * 128; i += stride) {
        int c = i >> 7, o = i & 127;
        g_Wt2[i] = (m2_g[o] / s) * m2_w[o * 128 + c];
        g_Wt3[i] = (m3_g[o] / s) * m3_w[o * 128 + c];
        g_Wc1[i] = (c1_g[o] / s) * c1_w[o * 128 + c];
        g_Wc2[i] = (c2_g[o] / s) * c2_w[o * 128 + c];
    }
    for (int o = t; o < 128; o += stride) {
        float a1 = m1_g[o] / s;
        g_beta1[o] = a1 * m1_b[o] + m1_be[o];
        g_Wg[o * 3 + 0] = a1 * m1_w[o * 259 + 0];
        g_Wg[o * 3 + 1] = a1 * m1_w[o * 259 + 1];
        g_Wg[o * 3 + 2] = a1 * m1_w[o * 259 + 2];
        g_bt2[o] = (m2_g[o] / s) * m2_b[o] + m2_be[o];
        g_bt3[o] = (m3_g[o] / s) * m3_b[o] + m3_be[o];
        g_bc1[o] = (c1_g[o] / s) * c1_b[o] + c1_be[o];
        g_bc2[o] = (c2_g[o] / s) * c2_b[o] + c2_be[o];
    }
}

// ---------------- transpose xyz (B,M,K,3) -> (n=b*19+k, M, 3) ----------------
__global__ void kx_kernel(const float* xyz) {
    int i = blockIdx.x * blockDim.x + threadIdx.x;
    if (i >= NB * MPTS * 3) return;
    int d = i % 3;
    int m = (i / 3) & 1023;
    int n = i / (3 * MPTS);
    int b = n / 19, k = n - b * 19;
    g_x[i] = xyz[((b * MPTS + m) * 19 + k) * 3 + d];
}

// ---------------- FPS (bit-exact selection) ----------------
__global__ void fps_kernel(float* agg) {
    int n = blockIdx.x;
    __shared__ float xs[MPTS * 3];
    __shared__ float dist[MPTS];
    __shared__ float rv[256];
    __shared__ int   ri[256];
    __shared__ int   s_cur;
    __shared__ float cc[3];
    int t = threadIdx.x;
    for (int i = t; i < MPTS * 3; i += 256) xs[i] = g_x[n * MPTS * 3 + i];
    for (int i = t; i < MPTS; i += 256) dist[i] = 1e10f;
    if (t == 0) s_cur = 0;
    __syncthreads();
    for (int it = 0; it < NP; ++it) {
        int cur = s_cur;
        if (t < 3) {
            float v = xs[cur * 3 + t];
            cc[t] = v;
            agg[(n * NP + it) * 3 + t] = v;
        }
        __syncthreads();
        float bv = -1.0f; int bi = 0;
        float c0 = cc[0], c1 = cc[1], c2 = cc[2];
#pragma unroll
        for (int q = 0; q < 4; ++q) {
            int m = t * 4 + q;
            float dx = __fadd_rn(xs[m * 3 + 0], -c0);
            float dy = __fadd_rn(xs[m * 3 + 1], -c1);
            float dz = __fadd_rn(xs[m * 3 + 2], -c2);
            float d = __fadd_rn(__fadd_rn(__fmul_rn(dx, dx), __fmul_rn(dy, dy)), __fmul_rn(dz, dz));
            float dm = fminf(dist[m], d);
            dist[m] = dm;
            if (dm > bv) { bv = dm; bi = m; }   // ascending m -> strict > keeps first
        }
        rv[t] = bv; ri[t] = bi;
        __syncthreads();
        if (t < 32) {
            float v = rv[t]; int idx = ri[t];
            for (int j = t + 32; j < 256; j += 32) {
                if (rv[j] > v) { v = rv[j]; idx = ri[j]; }   // ri ascending in j
            }
#pragma unroll
            for (int off = 16; off; off >>= 1) {
                float ov = __shfl_down_sync(0xffffffffu, v, off);
                int   oi = __shfl_down_sync(0xffffffffu, idx, off);
                if (ov > v || (ov == v && oi < idx)) { v = ov; idx = oi; }
            }
            if (t == 0) s_cur = idx;
        }
        __syncthreads();
    }
}

// ---------------- ball query: first 128 in-radius indices (ascending) ----------------
__global__ void ballq_kernel(const float* agg) {
    int gw = (blockIdx.x * blockDim.x + threadIdx.x) >> 5;
    int lane = threadIdx.x & 31;
    if (gw >= NB * NP) return;
    int n = gw >> 7, p = gw & 127;
    float cx = agg[(n * NP + p) * 3 + 0];
    float cy = agg[(n * NP + p) * 3 + 1];
    float cz = agg[(n * NP + p) * 3 + 2];
    const float* xb = g_x + n * MPTS * 3;
    int base = (n * NP + p) * NS;
    int cnt = 0, firstIdx = 0;
    bool haveFirst = false;
    for (int m0 = 0; m0 < MPTS; m0 += 32) {
        int m = m0 + lane;
        float dx = __fadd_rn(xb[m * 3 + 0], -cx);
        float dy = __fadd_rn(xb[m * 3 + 1], -cy);
        float dz = __fadd_rn(xb[m * 3 + 2], -cz);
        float d2 = __fadd_rn(__fadd_rn(__fmul_rn(dx, dx), __fmul_rn(dy, dy)), __fmul_rn(dz, dz));
        bool in = d2 < R2C;
        unsigned mask = __ballot_sync(0xffffffffu, in);
        if (!haveFirst && mask) { firstIdx = m0 + __ffs(mask) - 1; haveFirst = true; }
        int pr = __popc(mask & ((1u << lane) - 1u));
        if (in && cnt + pr < NS) g_idx[base + cnt + pr] = m;
        cnt += __popc(mask);
        if (cnt >= NS) break;
    }
    if (cnt > NS) cnt = NS;
    for (int j = cnt + lane; j < NS; j += 32) g_idx[base + j] = firstIdx;
}

// ---------------- Ffs = alpha1 * (W1f @ f) : per-batch GEMM 128x1024x256 ----------------
__global__ void ffgemm_kernel(const float* features) {
    __shared__ float Ws[16 * 128];
    __shared__ float Bs[16 * 128];
    int n = blockIdx.y;
    int m0 = blockIdx.x * 128;
    int b = n / 19, k = n - b * 19;
    int fbase = ((b * 256) * 19 + k) * 1024;
    int t = threadIdx.x, tx = t & 15, ty = t >> 4;
    float acc[8][8];
#pragma unroll
    for (int j = 0; j < 8; ++j)
#pragma unroll
        for (int i = 0; i < 8; ++i) acc[j][i] = 0.0f;
    for (int c0 = 0; c0 < CIN; c0 += 16) {
        __syncthreads();
        for (int i = t; i < 2048; i += 256) {
            int cc = i >> 7, o = i & 127;
            Ws[i] = g_W1ft[(c0 + cc) * 128 + o];
            Bs[i] = features[fbase + (c0 + cc) * (19 * 1024) + m0 + o];
        }
        __syncthreads();
#pragma unroll
        for (int cc = 0; cc < 16; ++cc) {
            float4 w0 = *(const float4*)&Ws[cc * 128 + ty * 8];
            float4 w1 = *(const float4*)&Ws[cc * 128 + ty * 8 + 4];
            float4 h0 = *(const float4*)&Bs[cc * 128 + tx * 8];
            float4 h1 = *(const float4*)&Bs[cc * 128 + tx * 8 + 4];
            float wv[8] = {w0.x, w0.y, w0.z, w0.w, w1.x, w1.y, w1.z, w1.w};
            float hv[8] = {h0.x, h0.y, h0.z, h0.w, h1.x, h1.y, h1.z, h1.w};
#pragma unroll
            for (int j = 0; j < 8; ++j)
#pragma unroll
                for (int i = 0; i < 8; ++i) acc[j][i] += wv[j] * hv[i];
        }
    }
#pragma unroll
    for (int j = 0; j < 8; ++j) {
        int o = ty * 8 + j;
        float4 v0 = {acc[j][0], acc[j][1], acc[j][2], acc[j][3]};
        float4 v1 = {acc[j][4], acc[j][5], acc[j][6], acc[j][7]};
        *(float4*)&g_Ffs[(n * 128 + o) * MPTS + m0 + tx * 8] = v0;
        *(float4*)&g_Ffs[(n * 128 + o) * MPTS + m0 + tx * 8 + 4] = v1;
    }
}

// ---------------- shared 128x128x128 GEMM core (Wt in global [c][o], h in smem [c][s]) --------
__device__ __forceinline__ void gemm128(const float* __restrict__ Wt, const float* hsm,
                                        float acc[8][8], int tx, int ty) {
#pragma unroll
    for (int j = 0; j < 8; ++j)
#pragma unroll
        for (int i = 0; i < 8; ++i) acc[j][i] = 0.0f;
#pragma unroll 4
    for (int c = 0; c < 128; ++c) {
        float4 w0 = *(const float4*)(Wt + c * 128 + ty * 8);
        float4 w1 = *(const float4*)(Wt + c * 128 + ty * 8 + 4);
        float4 h0 = *(const float4*)(hsm + c * 128 + tx * 8);
        float4 h1 = *(const float4*)(hsm + c * 128 + tx * 8 + 4);
        float wv[8] = {w0.x, w0.y, w0.z, w0.w, w1.x, w1.y, w1.z, w1.w};
        float hv[8] = {h0.x, h0.y, h0.z, h0.w, h1.x, h1.y, h1.z, h1.w};
#pragma unroll
        for (int j = 0; j < 8; ++j)
#pragma unroll
            for (int i = 0; i < 8; ++i) acc[j][i] += wv[j] * hv[i];
    }
}

__device__ __forceinline__ void relu_store(float* hsm, const float acc[8][8],
                                           const float* __restrict__ bias, int tx, int ty) {
#pragma unroll
    for (int j = 0; j < 8; ++j) {
        int o = ty * 8 + j;
        float bz = bias[o];
        float4 v0, v1;
        v0.x = fmaxf(acc[j][0] + bz, 0.0f); v0.y = fmaxf(acc[j][1] + bz, 0.0f);
        v0.z = fmaxf(acc[j][2] + bz, 0.0f); v0.w = fmaxf(acc[j][3] + bz, 0.0f);
        v1.x = fmaxf(acc[j][4] + bz, 0.0f); v1.y = fmaxf(acc[j][5] + bz, 0.0f);
        v1.z = fmaxf(acc[j][6] + bz, 0.0f); v1.w = fmaxf(acc[j][7] + bz, 0.0f);
        *(float4*)(hsm + o * 128 + tx * 8) = v0;
        *(float4*)(hsm + o * 128 + tx * 8 + 4) = v1;
    }
}

// ---------------- fused per-(n,p): gather+layer1, layer2, layer3, max ----------------
__global__ void __launch_bounds__(256, 2) fused_kernel(const float* agg, float* featOut) {
    extern __shared__ float sm[];
    float* h = sm;                       // 128x128
    float* gxn = sm + 16384;             // 3x128
    int*   idxs = (int*)(sm + 16384 + 384);
    int p = blockIdx.x, n = blockIdx.y;
    int t = threadIdx.x;

    float cx = agg[(n * NP + p) * 3 + 0];
    float cy = agg[(n * NP + p) * 3 + 1];
    float cz = agg[(n * NP + p) * 3 + 2];
    if (t < 128) {
        int ix = g_idx[(n * NP + p) * NS + t];
        idxs[t] = ix;
        const float* xp = g_x + (n * MPTS + ix) * 3;
        gxn[t]       = (xp[0] - cx) / 0.15f;
        gxn[128 + t] = (xp[1] - cy) / 0.15f;
        gxn[256 + t] = (xp[2] - cz) / 0.15f;
    }
    __syncthreads();

    // layer 1: gather Ffs + xyz FMA + beta1, relu -> h[c][s]
    {
        int s = t & 127, half = t >> 7;
        int ix = idxs[s];
        float gx0 = gxn[s], gx1 = gxn[128 + s], gx2 = gxn[256 + s];
        const float* Fb = g_Ffs + (n * 128) * MPTS + ix;
        int o0 = half * 64;
#pragma unroll 4
        for (int oo = 0; oo < 64; ++oo) {
            int o = o0 + oo;
            float v = Fb[o * MPTS]
                    + g_Wg[o * 3 + 0] * gx0 + g_Wg[o * 3 + 1] * gx1 + g_Wg[o * 3 + 2] * gx2
                    + g_beta1[o];
            h[o * 128 + s] = fmaxf(v, 0.0f);
        }
    }
    __syncthreads();

    int tx = t & 15, ty = t >> 4;
    float acc[8][8];

    // layer 2
    gemm128(g_Wt2, h, acc, tx, ty);
    __syncthreads();
    relu_store(h, acc, g_bt2, tx, ty);
    __syncthreads();

    // layer 3 + max over s
    gemm128(g_Wt3, h, acc, tx, ty);
#pragma unroll
    for (int j = 0; j < 8; ++j) {
        int o = ty * 8 + j;
        float bz = g_bt3[o];
        float m = fmaxf(acc[j][0] + bz, 0.0f);
#pragma unroll
        for (int i = 1; i < 8; ++i) m = fmaxf(m, fmaxf(acc[j][i] + bz, 0.0f));
#pragma unroll
        for (int off = 8; off; off >>= 1)
            m = fmaxf(m, __shfl_xor_sync(0xffffffffu, m, off, 16));
        if (tx == 0) featOut[(n * 128 + o) * 128 + p] = m;
    }
}

// ---------------- head: c1, c2, per-K 5x128 projection + scores ----------------
__global__ void head_kernel(const float* featIn, const float* agg,
                            const float* op_w, const float* op_b, float* scores) {
    extern __shared__ float A[];   // 128x128
    int n = blockIdx.x, t = threadIdx.x;
    for (int i = t; i < 16384; i += 256) A[i] = featIn[n * 16384 + i];
    __syncthreads();
    int tx = t & 15, ty = t >> 4;
    float acc[8][8];

    gemm128(g_Wc1, A, acc, tx, ty);
    __syncthreads();
    relu_store(A, acc, g_bc1, tx, ty);
    __syncthreads();

    gemm128(g_Wc2, A, acc, tx, ty);
    __syncthreads();
    relu_store(A, acc, g_bc2, tx, ty);
    __syncthreads();

    if (t < 128) {
        int p = t;
        int k = n % 19;
#pragma unroll
        for (int r = 0; r < 5; ++r) {
            float s = op_b[k * 5 + r];
            const float* wr = op_w + (k * 5 + r) * 128;
#pragma unroll 4
            for (int c = 0; c < 128; ++c) s += wr[c] * A[c * 128 + p];
            if (r >= 2) s += agg[(n * NP + p) * 3 + (r - 2)];
            scores[(n * NP + p) * 5 + r] = s;
        }
    }
}

// ---------------- launch ----------------
extern "C" void kernel_launch(void* const* d_in, const int* in_sizes, int n_in,
                              void* d_out, int out_size) {
    const float* xyz      = (const float*)d_in[0];
    const float* features = (const float*)d_in[1];
    const float* m1_w = (const float*)d_in[2];
    const float* m1_b = (const float*)d_in[3];
    const float* m1_g = (const float*)d_in[4];
    const float* m1_be = (const float*)d_in[5];
    const float* m2_w = (const float*)d_in[6];
    const float* m2_b = (const float*)d_in[7];
    const float* m2_g = (const float*)d_in[8];
    const float* m2_be = (const float*)d_in[9];
    const float* m3_w = (const float*)d_in[10];
    const float* m3_b = (const float*)d_in[11];
    const float* m3_g = (const float*)d_in[12];
    const float* m3_be = (const float*)d_in[13];
    const float* c1_w = (const float*)d_in[14];
    const float* c1_b = (const float*)d_in[15];
    const float* c1_g = (const float*)d_in[16];
    const float* c1_be = (const float*)d_in[17];
    const float* c2_w = (const float*)d_in[18];
    const float* c2_b = (const float*)d_in[19];
    const float* c2_g = (const float*)d_in[20];
    const float* c2_be = (const float*)d_in[21];
    const float* op_w = (const float*)d_in[22];
    const float* op_b = (const float*)d_in[23];

    float* out = (float*)d_out;
    float* scores = out;                       // 2*19*128*5  = 24320
    float* agg    = out + 24320;               // 2*19*128*3  = 14592
    float* feat   = out + 38912;               // 2*19*128*128 = 622592

    prep_kernel<<<64, 256>>>(m1_w, m1_b, m1_g, m1_be, m2_w, m2_b, m2_g, m2_be,
                             m3_w, m3_b, m3_g, m3_be, c1_w, c1_b, c1_g, c1_be,
                             c2_w, c2_b, c2_g, c2_be);
    kx_kernel<<<(NB * MPTS * 3 + 255) / 256, 256>>>(xyz);
    fps_kernel<<<NB, 256>>>(agg);
    ballq_kernel<<<(NB * NP * 32 + 255) / 256, 256>>>(agg);
    ffgemm_kernel<<<dim3(8, NB), 256>>>(features);

    const int FUSED_SMEM = (16384 + 384 + 128) * 4;
    cudaFuncSetAttribute(fused_kernel, cudaFuncAttributeMaxDynamicSharedMemorySize, FUSED_SMEM);
    fused_kernel<<<dim3(NP, NB), 256, FUSED_SMEM>>>(agg, feat);

    cudaFuncSetAttribute(head_kernel, cudaFuncAttributeMaxDynamicSharedMemorySize, 65536);
    head_kernel<<<NB, 256, 65536>>>(feat, agg, op_w, op_b, scores);
}

// round 5
// speedup vs baseline: 1.8894x; 1.8894x over previous
#include <cuda_runtime.h>
#include <cuda_bf16.h>
#include <cstdint>
#include <math.h>

#define NB    38          // B*K = 2*19
#define MPTS  1024
#define NP    128
#define NS    128
#define CIN   256
#define R2C   0.0225f
#define NTILE (NB * NP)   // 4864

// ================= helpers =================
__device__ __forceinline__ uint32_t smem_u32(const void* p) {
    uint32_t a;
    asm("{ .reg .u64 t; cvta.to.shared.u64 t, %1; cvt.u32.u64 %0, t; }" : "=r"(a) : "l"(p));
    return a;
}

// K-major swizzled row layout: 256B per row (128 bf16), 16B chunks q 0..15,
// physical chunk = q ^ (row & 7)   -> conflict-free ldmatrix & stores
__device__ __forceinline__ uint32_t swz_off(int row, int q) {
    return (uint32_t)(row * 256 + ((q ^ (row & 7)) << 4));
}

__device__ __forceinline__ void ldsm4(uint32_t addr, uint32_t r[4]) {
    asm volatile("ldmatrix.sync.aligned.m8n8.x4.shared.b16 {%0,%1,%2,%3}, [%4];"
        : "=r"(r[0]), "=r"(r[1]), "=r"(r[2]), "=r"(r[3]) : "r"(addr));
}

__device__ __forceinline__ void mma16816(float c[4], const uint32_t a[4], const uint32_t b[2]) {
    asm volatile("mma.sync.aligned.m16n8k16.row.col.f32.bf16.bf16.f32 "
        "{%0,%1,%2,%3}, {%4,%5,%6,%7}, {%8,%9}, {%0,%1,%2,%3};"
        : "+f"(c[0]), "+f"(c[1]), "+f"(c[2]), "+f"(c[3])
        : "r"(a[0]), "r"(a[1]), "r"(a[2]), "r"(a[3]), "r"(b[0]), "r"(b[1]));
}

// ================= scratch =================
__device__ float g_x[NB * MPTS * 3];
__device__ int   g_idx[NB * NP * NS];
__device__ float g_FfT[NB * MPTS * 128];    // [n][m][c]  (m-major)
__device__ float g_W1ft[CIN * 128];         // [c][o], alpha1-folded (for ffgemm)
__device__ float g_Wg[128 * 3];
__device__ float g_beta1[128];
__device__ float g_bt2[128];
__device__ float g_bt3[128];
__device__ float g_Wc1[128 * 128];
__device__ float g_bc1[128];
__device__ float g_Wc2[128 * 128];
__device__ float g_bc2[128];
// pre-swizzled bf16 weight images (K-major rows, swz_off layout):
// [0]=W2hi [1]=W2lo [2]=W3hi [3]=W3lo
__device__ char  g_Wimg[4][32768];

// ================= prep =================
__global__ void prep_kernel(const float* m1_w, const float* m1_b, const float* m1_g, const float* m1_be,
                            const float* m2_w, const float* m2_b, const float* m2_g, const float* m2_be,
                            const float* m3_w, const float* m3_b, const float* m3_g, const float* m3_be,
                            const float* c1_w, const float* c1_b, const float* c1_g, const float* c1_be,
                            const float* c2_w, const float* c2_b, const float* c2_g, const float* c2_be) {
    const float s = sqrtf(1.0f + 1e-5f);
    int t = blockIdx.x * blockDim.x + threadIdx.x;
    int stride = gridDim.x * blockDim.x;
    for (int i = t; i < CIN * 128; i += stride) {
        int c = i >> 7, o = i & 127;
        g_W1ft[i] = (m1_g[o] / s) * m1_w[o * 259 + 3 + c];
    }
    for (int i = t; i < 128 * 128; i += stride) {
        int c = i >> 7, o = i & 127;
        g_Wc1[i] = (c1_g[o] / s) * c1_w[o * 128 + c];
        g_Wc2[i] = (c2_g[o] / s) * c2_w[o * 128 + c];
    }
    // bf16 hi/lo swizzled images for W2, W3 (row = o, K = c)
    for (int i = t; i < 2 * 128 * 16; i += stride) {
        int mat = i >> 11;              // 0 = W2, 1 = W3
        int rem = i & 2047;
        int o = rem >> 4, q = rem & 15;
        const float* w = mat ? m3_w : m2_w;
        const float* gg = mat ? m3_g : m2_g;
        float alpha = gg[o] / s;
        uint4 uh, ul;
        uint32_t* ph = (uint32_t*)&uh;
        uint32_t* pl = (uint32_t*)&ul;
#pragma unroll
        for (int k = 0; k < 4; ++k) {
            float a = alpha * w[o * 128 + q * 8 + 2 * k];
            float b = alpha * w[o * 128 + q * 8 + 2 * k + 1];
            __nv_bfloat16 ha = __float2bfloat16(a), hb = __float2bfloat16(b);
            float la = a - __bfloat162float(ha), lb = b - __bfloat162float(hb);
            __nv_bfloat16 loa = __float2bfloat16(la), lob = __float2bfloat16(lb);
            ph[k] = ((uint32_t)__bfloat16_as_ushort(hb) << 16) | __bfloat16_as_ushort(ha);
            pl[k] = ((uint32_t)__bfloat16_as_ushort(lob) << 16) | __bfloat16_as_ushort(loa);
        }
        uint32_t off = swz_off(o, q);
        *(uint4*)(g_Wimg[mat * 2 + 0] + off) = uh;
        *(uint4*)(g_Wimg[mat * 2 + 1] + off) = ul;
    }
    for (int o = t; o < 128; o += stride) {
        float a1 = m1_g[o] / s;
        g_beta1[o] = a1 * m1_b[o] + m1_be[o];
        g_Wg[o * 3 + 0] = a1 * m1_w[o * 259 + 0];
        g_Wg[o * 3 + 1] = a1 * m1_w[o * 259 + 1];
        g_Wg[o * 3 + 2] = a1 * m1_w[o * 259 + 2];
        g_bt2[o] = (m2_g[o] / s) * m2_b[o] + m2_be[o];
        g_bt3[o] = (m3_g[o] / s) * m3_b[o] + m3_be[o];
        g_bc1[o] = (c1_g[o] / s) * c1_b[o] + c1_be[o];
        g_bc2[o] = (c2_g[o] / s) * c2_b[o] + c2_be[o];
    }
}

// ================= transpose xyz =================
__global__ void kx_kernel(const float* xyz) {
    int i = blockIdx.x * blockDim.x + threadIdx.x;
    if (i >= NB * MPTS * 3) return;
    int d = i % 3;
    int m = (i / 3) & 1023;
    int n = i / (3 * MPTS);
    int b = n / 19, k = n - b * 19;
    g_x[i] = xyz[((b * MPTS + m) * 19 + k) * 3 + d];
}

// ================= FPS (bit-exact selection) =================
__global__ void fps_kernel(float* agg) {
    int n = blockIdx.x;
    __shared__ float xs[MPTS * 3];
    __shared__ float dist[MPTS];
    __shared__ float rv[256];
    __shared__ int   ri[256];
    __shared__ int   s_cur;
    __shared__ float cc[3];
    int t = threadIdx.x;
    for (int i = t; i < MPTS * 3; i += 256) xs[i] = g_x[n * MPTS * 3 + i];
    for (int i = t; i < MPTS; i += 256) dist[i] = 1e10f;
    if (t == 0) s_cur = 0;
    __syncthreads();
    for (int it = 0; it < NP; ++it) {
        int cur = s_cur;
        if (t < 3) {
            float v = xs[cur * 3 + t];
            cc[t] = v;
            agg[(n * NP + it) * 3 + t] = v;
        }
        __syncthreads();
        float bv = -1.0f; int bi = 0;
        float c0 = cc[0], c1 = cc[1], c2 = cc[2];
#pragma unroll
        for (int q = 0; q < 4; ++q) {
            int m = t * 4 + q;
            float dx = __fadd_rn(xs[m * 3 + 0], -c0);
            float dy = __fadd_rn(xs[m * 3 + 1], -c1);
            float dz = __fadd_rn(xs[m * 3 + 2], -c2);
            float d = __fadd_rn(__fadd_rn(__fmul_rn(dx, dx), __fmul_rn(dy, dy)), __fmul_rn(dz, dz));
            float dm = fminf(dist[m], d);
            dist[m] = dm;
            if (dm > bv) { bv = dm; bi = m; }
        }
        rv[t] = bv; ri[t] = bi;
        __syncthreads();
        if (t < 32) {
            float v = rv[t]; int idx = ri[t];
            for (int j = t + 32; j < 256; j += 32) {
                if (rv[j] > v) { v = rv[j]; idx = ri[j]; }
            }
#pragma unroll
            for (int off = 16; off; off >>= 1) {
                float ov = __shfl_down_sync(0xffffffffu, v, off);
                int   oi = __shfl_down_sync(0xffffffffu, idx, off);
                if (ov > v || (ov == v && oi < idx)) { v = ov; idx = oi; }
            }
            if (t == 0) s_cur = idx;
        }
        __syncthreads();
    }
}

// ================= ball query =================
__global__ void ballq_kernel(const float* agg) {
    int gw = (blockIdx.x * blockDim.x + threadIdx.x) >> 5;
    int lane = threadIdx.x & 31;
    if (gw >= NB * NP) return;
    int n = gw >> 7, p = gw & 127;
    float cx = agg[(n * NP + p) * 3 + 0];
    float cy = agg[(n * NP + p) * 3 + 1];
    float cz = agg[(n * NP + p) * 3 + 2];
    const float* xb = g_x + n * MPTS * 3;
    int base = (n * NP + p) * NS;
    int cnt = 0, firstIdx = 0;
    bool haveFirst = false;
    for (int m0 = 0; m0 < MPTS; m0 += 32) {
        int m = m0 + lane;
        float dx = __fadd_rn(xb[m * 3 + 0], -cx);
        float dy = __fadd_rn(xb[m * 3 + 1], -cy);
        float dz = __fadd_rn(xb[m * 3 + 2], -cz);
        float d2 = __fadd_rn(__fadd_rn(__fmul_rn(dx, dx), __fmul_rn(dy, dy)), __fmul_rn(dz, dz));
        bool in = d2 < R2C;
        unsigned mask = __ballot_sync(0xffffffffu, in);
        if (!haveFirst && mask) { firstIdx = m0 + __ffs(mask) - 1; haveFirst = true; }
        int pr = __popc(mask & ((1u << lane) - 1u));
        if (in && cnt + pr < NS) g_idx[base + cnt + pr] = m;
        cnt += __popc(mask);
        if (cnt >= NS) break;
    }
    if (cnt > NS) cnt = NS;
    for (int j = cnt + lane; j < NS; j += 32) g_idx[base + j] = firstIdx;
}

// ================= FfT = alpha1 * (W1f @ f), stored [n][m][c] =================
__global__ void ffgemm_kernel(const float* features) {
    __shared__ float Ws[16 * 128];
    __shared__ float Bs[16 * 128];
    int n = blockIdx.y;
    int m0 = blockIdx.x * 128;
    int b = n / 19, k = n - b * 19;
    int fbase = ((b * 256) * 19 + k) * 1024;
    int t = threadIdx.x, tx = t & 15, ty = t >> 4;
    float acc[8][8];
#pragma unroll
    for (int j = 0; j < 8; ++j)
#pragma unroll
        for (int i = 0; i < 8; ++i) acc[j][i] = 0.0f;
    for (int c0 = 0; c0 < CIN; c0 += 16) {
        __syncthreads();
        for (int i = t; i < 2048; i += 256) {
            int cc = i >> 7, o = i & 127;
            Ws[i] = g_W1ft[(c0 + cc) * 128 + o];
            Bs[i] = features[fbase + (c0 + cc) * (19 * 1024) + m0 + o];
        }
        __syncthreads();
#pragma unroll
        for (int cc = 0; cc < 16; ++cc) {
            float4 w0 = *(const float4*)&Ws[cc * 128 + ty * 8];
            float4 w1 = *(const float4*)&Ws[cc * 128 + ty * 8 + 4];
            float4 h0 = *(const float4*)&Bs[cc * 128 + tx * 8];
            float4 h1 = *(const float4*)&Bs[cc * 128 + tx * 8 + 4];
            float wv[8] = {w0.x, w0.y, w0.z, w0.w, w1.x, w1.y, w1.z, w1.w};
            float hv[8] = {h0.x, h0.y, h0.z, h0.w, h1.x, h1.y, h1.z, h1.w};
#pragma unroll
            for (int j = 0; j < 8; ++j)
#pragma unroll
                for (int i = 0; i < 8; ++i) acc[j][i] += wv[j] * hv[i];
        }
    }
#pragma unroll
    for (int i = 0; i < 8; ++i) {
        int m = m0 + tx * 8 + i;
        float4 v0 = {acc[0][i], acc[1][i], acc[2][i], acc[3][i]};
        float4 v1 = {acc[4][i], acc[5][i], acc[6][i], acc[7][i]};
        *(float4*)&g_FfT[((n << 10) + m) * 128 + ty * 8] = v0;
        *(float4*)&g_FfT[((n << 10) + m) * 128 + ty * 8 + 4] = v1;
    }
}

// ================= split-bf16 helpers =================
__device__ __forceinline__ void split_store8(char* hiB, char* loB, uint32_t off, const float* v) {
    uint4 uh, ul;
    uint32_t* ph = (uint32_t*)&uh;
    uint32_t* pl = (uint32_t*)&ul;
#pragma unroll
    for (int k = 0; k < 4; ++k) {
        float a = v[2 * k], b = v[2 * k + 1];
        __nv_bfloat16 ha = __float2bfloat16(a), hb = __float2bfloat16(b);
        float la = a - __bfloat162float(ha), lb = b - __bfloat162float(hb);
        __nv_bfloat16 loa = __float2bfloat16(la), lob = __float2bfloat16(lb);
        ph[k] = ((uint32_t)__bfloat16_as_ushort(hb) << 16) | __bfloat16_as_ushort(ha);
        pl[k] = ((uint32_t)__bfloat16_as_ushort(lob) << 16) | __bfloat16_as_ushort(loa);
    }
    *(uint4*)(hiB + off) = uh;
    *(uint4*)(loB + off) = ul;
}

__device__ __forceinline__ void split_pair_store(char* hiB, char* loB, int row, int co,
                                                 float a, float b) {
    int chunk = co >> 3;
    uint32_t off = (uint32_t)(row * 256 + ((chunk ^ (row & 7)) << 4) + (co & 7) * 2);
    __nv_bfloat16 ha = __float2bfloat16(a), hb = __float2bfloat16(b);
    float la = a - __bfloat162float(ha), lb = b - __bfloat162float(hb);
    __nv_bfloat16 loa = __float2bfloat16(la), lob = __float2bfloat16(lb);
    *(uint32_t*)(hiB + off) = ((uint32_t)__bfloat16_as_ushort(hb) << 16) | __bfloat16_as_ushort(ha);
    *(uint32_t*)(loB + off) = ((uint32_t)__bfloat16_as_ushort(lob) << 16) | __bfloat16_as_ushort(loa);
}

// 128x128x128 GEMM, split-bf16 (AhBh + AhBl + AlBh), warp tile m32 x n64 (warps 4x2)
__device__ __forceinline__ void gemm_split(float acc[2][8][4],
        uint32_t aHi, uint32_t aLo, uint32_t bHi, uint32_t bLo,
        int wm, int wn, int lane) {
    int arow = wm * 32 + (lane & 7) + ((lane >> 3) & 1) * 8;   // + mt*16
    int ach  = (lane >> 4);                                    // + k*2
    int brow = wn * 64 + (lane & 7) + (lane >> 4) * 8;         // + ntp*16
    int bch  = ((lane >> 3) & 1);                              // + k*2
#pragma unroll
    for (int k = 0; k < 8; ++k) {
        uint32_t ah[2][4], al[2][4], bh[8][2], bl[8][2];
#pragma unroll
        for (int mt = 0; mt < 2; ++mt) {
            int r = arow + mt * 16;
            uint32_t base = (uint32_t)(r * 256 + (((ach + k * 2) ^ (r & 7)) << 4));
            ldsm4(aHi + base, ah[mt]);
            ldsm4(aLo + base, al[mt]);
        }
#pragma unroll
        for (int ntp = 0; ntp < 4; ++ntp) {
            int r = brow + ntp * 16;
            uint32_t base = (uint32_t)(r * 256 + (((bch + k * 2) ^ (r & 7)) << 4));
            uint32_t rr[4];
            ldsm4(bHi + base, rr);
            bh[2 * ntp][0] = rr[0]; bh[2 * ntp][1] = rr[1];
            bh[2 * ntp + 1][0] = rr[2]; bh[2 * ntp + 1][1] = rr[3];
            ldsm4(bLo + base, rr);
            bl[2 * ntp][0] = rr[0]; bl[2 * ntp][1] = rr[1];
            bl[2 * ntp + 1][0] = rr[2]; bl[2 * ntp + 1][1] = rr[3];
        }
#pragma unroll
        for (int mt = 0; mt < 2; ++mt)
#pragma unroll
            for (int nt = 0; nt < 8; ++nt)
                mma16816(acc[mt][nt], ah[mt], bh[nt]);
#pragma unroll
        for (int mt = 0; mt < 2; ++mt)
#pragma unroll
            for (int nt = 0; nt < 8; ++nt)
                mma16816(acc[mt][nt], ah[mt], bl[nt]);
#pragma unroll
        for (int mt = 0; mt < 2; ++mt)
#pragma unroll
            for (int nt = 0; nt < 8; ++nt)
                mma16816(acc[mt][nt], al[mt], bh[nt]);
    }
}

// ================= fused persistent kernel =================
// smem layout:
//   0       W2hi | 32768 W2lo | 65536 W3hi | 98304 W3lo
//   131072  Hhi  | 163840 Hlo            (h1 then h2, reused)
//   196608  sWg(1536) | 198144 sBeta(512) | 198656 sB2(512) | 199168 sB3(512)
//   199680  sRed(1024)  -> total 200704
#define FUSED_SMEM_BYTES 200704

__global__ void __launch_bounds__(256, 1) fused_kernel(const float* agg, float* featOut) {
    extern __shared__ char sm[];
    char* sHhi = sm + 131072;
    char* sHlo = sm + 163840;
    float* sWg   = (float*)(sm + 196608);
    float* sBeta = (float*)(sm + 198144);
    float* sB2   = (float*)(sm + 198656);
    float* sB3   = (float*)(sm + 199168);
    float* sRed  = (float*)(sm + 199680);
    uint32_t smbase = smem_u32(sm);
    const uint32_t aHhi = smbase + 131072;
    const uint32_t aHlo = smbase + 163840;
    const uint32_t aW2hi = smbase + 0;
    const uint32_t aW2lo = smbase + 32768;
    const uint32_t aW3hi = smbase + 65536;
    const uint32_t aW3lo = smbase + 98304;

    int t = threadIdx.x;
    int warp = t >> 5, lane = t & 31;
    int wm = warp >> 1, wn = warp & 1;
    int row = t & 127;
    int half = t >> 7;
    int cbase = half * 64;

    // load weight images + consts (once)
    {
        const uint4* src = (const uint4*)g_Wimg;
        uint4* dst = (uint4*)sm;
        for (int i = t; i < 8192; i += 256) dst[i] = src[i];
        for (int i = t; i < 384; i += 256) sWg[i] = g_Wg[i];
        if (t < 128) { sBeta[t] = g_beta1[t]; sB2[t] = g_bt2[t]; sB3[t] = g_bt3[t]; }
    }
    __syncthreads();

    for (int tile = blockIdx.x; tile < NTILE; tile += gridDim.x) {
        int n = tile >> 7, p = tile & 127;

        // ---- layer 1: gather FfT rows + xyz FMA + beta, relu, split-store h1 [s][c]
        {
            int s = row;
            int ix = g_idx[((n << 7) | p) * NS + s];
            float cx = agg[((n << 7) | p) * 3 + 0];
            float cy = agg[((n << 7) | p) * 3 + 1];
            float cz = agg[((n << 7) | p) * 3 + 2];
            const float* xp = g_x + (n * MPTS + ix) * 3;
            float g0 = (xp[0] - cx) / 0.15f;
            float g1 = (xp[1] - cy) / 0.15f;
            float g2 = (xp[2] - cz) / 0.15f;
            const float4* fb = (const float4*)(g_FfT + (((n << 10) + ix) << 7) + cbase);
#pragma unroll
            for (int qq = 0; qq < 8; ++qq) {
                float4 a = fb[qq * 2], b = fb[qq * 2 + 1];
                float v[8] = {a.x, a.y, a.z, a.w, b.x, b.y, b.z, b.w};
#pragma unroll
                for (int j = 0; j < 8; ++j) {
                    int c = cbase + qq * 8 + j;
                    float w = v[j] + sWg[c * 3 + 0] * g0 + sWg[c * 3 + 1] * g1
                                   + sWg[c * 3 + 2] * g2 + sBeta[c];
                    v[j] = fmaxf(w, 0.0f);
                }
                split_store8(sHhi, sHlo, swz_off(s, half * 8 + qq), v);
            }
        }
        __syncthreads();

        float acc[2][8][4];

        // ---- layer 2: D2[s][o2] = h1 @ W2^T
#pragma unroll
        for (int mt = 0; mt < 2; ++mt)
#pragma unroll
            for (int nt = 0; nt < 8; ++nt)
#pragma unroll
                for (int i = 0; i < 4; ++i) acc[mt][nt][i] = 0.0f;
        gemm_split(acc, aHhi, aHlo, aW2hi, aW2lo, wm, wn, lane);
        __syncthreads();   // all h1 reads done before overwrite

        // epilogue: bias+relu, split-store h2 [s][o2]
#pragma unroll
        for (int mt = 0; mt < 2; ++mt) {
            int r0 = wm * 32 + mt * 16 + (lane >> 2);
#pragma unroll
            for (int nt = 0; nt < 8; ++nt) {
                int co = wn * 64 + nt * 8 + (lane & 3) * 2;
                float b0 = sB2[co], b1 = sB2[co + 1];
                split_pair_store(sHhi, sHlo, r0, co,
                                 fmaxf(acc[mt][nt][0] + b0, 0.0f),
                                 fmaxf(acc[mt][nt][1] + b1, 0.0f));
                split_pair_store(sHhi, sHlo, r0 + 8, co,
                                 fmaxf(acc[mt][nt][2] + b0, 0.0f),
                                 fmaxf(acc[mt][nt][3] + b1, 0.0f));
            }
        }
        __syncthreads();

        // ---- layer 3: D3[o3][s] = W3 @ h2^T
#pragma unroll
        for (int mt = 0; mt < 2; ++mt)
#pragma unroll
            for (int nt = 0; nt < 8; ++nt)
#pragma unroll
                for (int i = 0; i < 4; ++i) acc[mt][nt][i] = 0.0f;
        gemm_split(acc, aW3hi, aW3lo, aHhi, aHlo, wm, wn, lane);

        // reduce max over s (cols) in-register, then quad shuffle, then smem combine
#pragma unroll
        for (int mt = 0; mt < 2; ++mt) {
            float m0 = -1e30f, m1 = -1e30f;
#pragma unroll
            for (int nt = 0; nt < 8; ++nt) {
                m0 = fmaxf(m0, fmaxf(acc[mt][nt][0], acc[mt][nt][1]));
                m1 = fmaxf(m1, fmaxf(acc[mt][nt][2], acc[mt][nt][3]));
            }
            m0 = fmaxf(m0, __shfl_xor_sync(0xffffffffu, m0, 1));
            m0 = fmaxf(m0, __shfl_xor_sync(0xffffffffu, m0, 2));
            m1 = fmaxf(m1, __shfl_xor_sync(0xffffffffu, m1, 1));
            m1 = fmaxf(m1, __shfl_xor_sync(0xffffffffu, m1, 2));
            if ((lane & 3) == 0) {
                int r0 = wm * 32 + mt * 16 + (lane >> 2);
                sRed[r0 * 2 + wn] = m0;
                sRed[(r0 + 8) * 2 + wn] = m1;
            }
        }
        __syncthreads();
        if (t < 128) {
            float v = fmaxf(sRed[t * 2], sRed[t * 2 + 1]);
            featOut[(((n << 7) | t) << 7) | p] = fmaxf(v + sB3[t], 0.0f);
        }
        __syncthreads();
    }
}

// ================= fp32 128-GEMM helpers (head) =================
__device__ __forceinline__ void gemm128(const float* __restrict__ Wt, const float* hsm,
                                        float acc[8][8], int tx, int ty) {
#pragma unroll
    for (int j = 0; j < 8; ++j)
#pragma unroll
        for (int i = 0; i < 8; ++i) acc[j][i] = 0.0f;
#pragma unroll 4
    for (int c = 0; c < 128; ++c) {
        float4 w0 = *(const float4*)(Wt + c * 128 + ty * 8);
        float4 w1 = *(const float4*)(Wt + c * 128 + ty * 8 + 4);
        float4 h0 = *(const float4*)(hsm + c * 128 + tx * 8);
        float4 h1 = *(const float4*)(hsm + c * 128 + tx * 8 + 4);
        float wv[8] = {w0.x, w0.y, w0.z, w0.w, w1.x, w1.y, w1.z, w1.w};
        float hv[8] = {h0.x, h0.y, h0.z, h0.w, h1.x, h1.y, h1.z, h1.w};
#pragma unroll
        for (int j = 0; j < 8; ++j)
#pragma unroll
            for (int i = 0; i < 8; ++i) acc[j][i] += wv[j] * hv[i];
    }
}

__device__ __forceinline__ void relu_store(float* hsm, const float acc[8][8],
                                           const float* __restrict__ bias, int tx, int ty) {
#pragma unroll
    for (int j = 0; j < 8; ++j) {
        int o = ty * 8 + j;
        float bz = bias[o];
        float4 v0, v1;
        v0.x = fmaxf(acc[j][0] + bz, 0.0f); v0.y = fmaxf(acc[j][1] + bz, 0.0f);
        v0.z = fmaxf(acc[j][2] + bz, 0.0f); v0.w = fmaxf(acc[j][3] + bz, 0.0f);
        v1.x = fmaxf(acc[j][4] + bz, 0.0f); v1.y = fmaxf(acc[j][5] + bz, 0.0f);
        v1.z = fmaxf(acc[j][6] + bz, 0.0f); v1.w = fmaxf(acc[j][7] + bz, 0.0f);
        *(float4*)(hsm + o * 128 + tx * 8) = v0;
        *(float4*)(hsm + o * 128 + tx * 8 + 4) = v1;
    }
}

// ================= head =================
__global__ void head_kernel(const float* featIn, const float* agg,
                            const float* op_w, const float* op_b, float* scores) {
    extern __shared__ float A[];
    int n = blockIdx.x, t = threadIdx.x;
    for (int i = t; i < 16384; i += 256) A[i] = featIn[n * 16384 + i];
    __syncthreads();
    int tx = t & 15, ty = t >> 4;
    float acc[8][8];

    gemm128(g_Wc1, A, acc, tx, ty);
    __syncthreads();
    relu_store(A, acc, g_bc1, tx, ty);
    __syncthreads();

    gemm128(g_Wc2, A, acc, tx, ty);
    __syncthreads();
    relu_store(A, acc, g_bc2, tx, ty);
    __syncthreads();

    if (t < 128) {
        int p = t;
        int k = n % 19;
#pragma unroll
        for (int r = 0; r < 5; ++r) {
            float s = op_b[k * 5 + r];
            const float* wr = op_w + (k * 5 + r) * 128;
#pragma unroll 4
            for (int c = 0; c < 128; ++c) s += wr[c] * A[c * 128 + p];
            if (r >= 2) s += agg[(n * NP + p) * 3 + (r - 2)];
            scores[(n * NP + p) * 5 + r] = s;
        }
    }
}

// ================= launch =================
extern "C" void kernel_launch(void* const* d_in, const int* in_sizes, int n_in,
                              void* d_out, int out_size) {
    const float* xyz      = (const float*)d_in[0];
    const float* features = (const float*)d_in[1];
    const float* m1_w = (const float*)d_in[2];
    const float* m1_b = (const float*)d_in[3];
    const float* m1_g = (const float*)d_in[4];
    const float* m1_be = (const float*)d_in[5];
    const float* m2_w = (const float*)d_in[6];
    const float* m2_b = (const float*)d_in[7];
    const float* m2_g = (const float*)d_in[8];
    const float* m2_be = (const float*)d_in[9];
    const float* m3_w = (const float*)d_in[10];
    const float* m3_b = (const float*)d_in[11];
    const float* m3_g = (const float*)d_in[12];
    const float* m3_be = (const float*)d_in[13];
    const float* c1_w = (const float*)d_in[14];
    const float* c1_b = (const float*)d_in[15];
    const float* c1_g = (const float*)d_in[16];
    const float* c1_be = (const float*)d_in[17];
    const float* c2_w = (const float*)d_in[18];
    const float* c2_b = (const float*)d_in[19];
    const float* c2_g = (const float*)d_in[20];
    const float* c2_be = (const float*)d_in[21];
    const float* op_w = (const float*)d_in[22];
    const float* op_b = (const float*)d_in[23];

    float* out = (float*)d_out;
    float* scores = out;                       // 2*19*128*5
    float* agg    = out + 24320;               // 2*19*128*3
    float* feat   = out + 38912;               // 2*19*128*128

    prep_kernel<<<64, 256>>>(m1_w, m1_b, m1_g, m1_be, m2_w, m2_b, m2_g, m2_be,
                             m3_w, m3_b, m3_g, m3_be, c1_w, c1_b, c1_g, c1_be,
                             c2_w, c2_b, c2_g, c2_be);
    kx_kernel<<<(NB * MPTS * 3 + 255) / 256, 256>>>(xyz);
    fps_kernel<<<NB, 256>>>(agg);
    ballq_kernel<<<(NB * NP * 32 + 255) / 256, 256>>>(agg);
    ffgemm_kernel<<<dim3(8, NB), 256>>>(features);

    cudaFuncSetAttribute(fused_kernel, cudaFuncAttributeMaxDynamicSharedMemorySize, FUSED_SMEM_BYTES);
    fused_kernel<<<148, 256, FUSED_SMEM_BYTES>>>(agg, feat);

    cudaFuncSetAttribute(head_kernel, cudaFuncAttributeMaxDynamicSharedMemorySize, 65536);
    head_kernel<<<NB, 256, 65536>>>(feat, agg, op_w, op_b, scores);
}

// round 8
// speedup vs baseline: 2.1906x; 1.1594x over previous
#include <cuda_runtime.h>
#include <cuda_bf16.h>
#include <cstdint>
#include <math.h>

#define NB    38          // B*K = 2*19
#define MPTS  1024
#define NP    128
#define NS    128
#define CIN   256
#define R2C   0.0225f
#define NTILE (NB * NP)   // 4864
#define LDH   132         // padded row stride (floats) -> conflict-free frags

// ================= helpers =================
__device__ __forceinline__ float tf32r(float x) {
    uint32_t u;
    asm("cvt.rna.tf32.f32 %0, %1;" : "=r"(u) : "f"(x));
    return __uint_as_float(u);
}

__device__ __forceinline__ void mma_tf32(float c[4], const uint32_t a[4], const uint32_t b[2]) {
    asm volatile("mma.sync.aligned.m16n8k8.row.col.f32.tf32.tf32.f32 "
        "{%0,%1,%2,%3}, {%4,%5,%6,%7}, {%8,%9}, {%0,%1,%2,%3};"
        : "+f"(c[0]), "+f"(c[1]), "+f"(c[2]), "+f"(c[3])
        : "r"(a[0]), "r"(a[1]), "r"(a[2]), "r"(a[3]), "r"(b[0]), "r"(b[1]));
}

// ================= scratch =================
__device__ float g_x[NB * MPTS * 3];
__device__ int   g_idx[NB * NP * NS];
__device__ float g_FfT[NB * MPTS * 128];    // [n][m][c]  (m-major)
__device__ float g_W1ft[CIN * 128];         // [c][o], alpha1-folded (for ffgemm)
__device__ float g_Wg[128 * 3];
__device__ float g_beta1[128];
__device__ float g_bt2[128];
__device__ float g_bt3[128];
__device__ float g_Wc1[128 * 128];
__device__ float g_bc1[128];
__device__ float g_Wc2[128 * 128];
__device__ float g_bc2[128];
// tf32-rounded, alpha-folded, padded [o][LDH] weight rows (K contiguous)
__device__ float g_W2t[128 * LDH];
__device__ float g_W3t[128 * LDH];

// ================= prep =================
__global__ void prep_kernel(const float* m1_w, const float* m1_b, const float* m1_g, const float* m1_be,
                            const float* m2_w, const float* m2_b, const float* m2_g, const float* m2_be,
                            const float* m3_w, const float* m3_b, const float* m3_g, const float* m3_be,
                            const float* c1_w, const float* c1_b, const float* c1_g, const float* c1_be,
                            const float* c2_w, const float* c2_b, const float* c2_g, const float* c2_be) {
    const float s = sqrtf(1.0f + 1e-5f);
    int t = blockIdx.x * blockDim.x + threadIdx.x;
    int stride = gridDim.x * blockDim.x;
    for (int i = t; i < CIN * 128; i += stride) {
        int c = i >> 7, o = i & 127;
        g_W1ft[i] = (m1_g[o] / s) * m1_w[o * 259 + 3 + c];
    }
    for (int i = t; i < 128 * 128; i += stride) {
        int c = i >> 7, o = i & 127;
        g_Wc1[i] = (c1_g[o] / s) * c1_w[o * 128 + c];
        g_Wc2[i] = (c2_g[o] / s) * c2_w[o * 128 + c];
        g_W2t[o * LDH + c] = tf32r((m2_g[o] / s) * m2_w[o * 128 + c]);
        g_W3t[o * LDH + c] = tf32r((m3_g[o] / s) * m3_w[o * 128 + c]);
    }
    for (int o = t; o < 128; o += stride) {
        float a1 = m1_g[o] / s;
        g_beta1[o] = a1 * m1_b[o] + m1_be[o];
        g_Wg[o * 3 + 0] = a1 * m1_w[o * 259 + 0];
        g_Wg[o * 3 + 1] = a1 * m1_w[o * 259 + 1];
        g_Wg[o * 3 + 2] = a1 * m1_w[o * 259 + 2];
        g_bt2[o] = (m2_g[o] / s) * m2_b[o] + m2_be[o];
        g_bt3[o] = (m3_g[o] / s) * m3_b[o] + m3_be[o];
        g_bc1[o] = (c1_g[o] / s) * c1_b[o] + c1_be[o];
        g_bc2[o] = (c2_g[o] / s) * c2_b[o] + c2_be[o];
    }
}

// ================= ffgemm part (FfT = alpha1 * (W1f @ f), stored [n][m][c]) =============
__device__ void ffgemm_part(const float* features, float* cs, int ffidx, int t) {
    float* Ws = cs;              // 16*128
    float* Bs = cs + 2048;       // 16*128
    int n = ffidx >> 3;
    int m0 = (ffidx & 7) << 7;
    int b = n / 19, k = n - b * 19;
    int fbase = ((b * 256) * 19 + k) * 1024;
    int tx = t & 15, ty = t >> 4;
    float acc[8][8];
#pragma unroll
    for (int j = 0; j < 8; ++j)
#pragma unroll
        for (int i = 0; i < 8; ++i) acc[j][i] = 0.0f;
    for (int c0 = 0; c0 < CIN; c0 += 16) {
        __syncthreads();
        for (int i = t; i < 2048; i += 256) {
            int cc = i >> 7, o = i & 127;
            Ws[i] = g_W1ft[(c0 + cc) * 128 + o];
            Bs[i] = features[fbase + (c0 + cc) * (19 * 1024) + m0 + o];
        }
        __syncthreads();
#pragma unroll
        for (int cc = 0; cc < 16; ++cc) {
            float4 w0 = *(const float4*)&Ws[cc * 128 + ty * 8];
            float4 w1 = *(const float4*)&Ws[cc * 128 + ty * 8 + 4];
            float4 h0 = *(const float4*)&Bs[cc * 128 + tx * 8];
            float4 h1 = *(const float4*)&Bs[cc * 128 + tx * 8 + 4];
            float wv[8] = {w0.x, w0.y, w0.z, w0.w, w1.x, w1.y, w1.z, w1.w};
            float hv[8] = {h0.x, h0.y, h0.z, h0.w, h1.x, h1.y, h1.z, h1.w};
#pragma unroll
            for (int j = 0; j < 8; ++j)
#pragma unroll
                for (int i = 0; i < 8; ++i) acc[j][i] += wv[j] * hv[i];
        }
    }
#pragma unroll
    for (int i = 0; i < 8; ++i) {
        int m = m0 + tx * 8 + i;
        float4 v0 = {acc[0][i], acc[1][i], acc[2][i], acc[3][i]};
        float4 v1 = {acc[4][i], acc[5][i], acc[6][i], acc[7][i]};
        *(float4*)&g_FfT[((n << 10) + m) * 128 + ty * 8] = v0;
        *(float4*)&g_FfT[((n << 10) + m) * 128 + ty * 8 + 4] = v1;
    }
}

// ================= combo1: fps (reads xyz directly, writes g_x) || ffgemm[0:152] =========
__global__ void combo1_kernel(const float* xyz, const float* features, float* agg) {
    extern __shared__ float cs[];
    int t = threadIdx.x;
    if (blockIdx.x >= NB) {
        ffgemm_part(features, cs, blockIdx.x - NB, t);
        return;
    }
    // ---- FPS (bit-exact selection) ----
    int n = blockIdx.x;
    float* xs   = cs;                 // 3072
    float* dist = cs + 3072;          // 1024
    float* rv   = cs + 4096;          // 256
    int*   ri   = (int*)(cs + 4352);  // 256
    int*   s_cur = (int*)(cs + 4608);
    float* cc   = cs + 4609;          // 3
    int b = n / 19, k = n - b * 19;
    for (int i = t; i < MPTS * 3; i += 256) {
        int m = i / 3, d = i - m * 3;
        float v = xyz[(((b << 10) | m) * 19 + k) * 3 + d];
        xs[i] = v;
        g_x[n * (MPTS * 3) + i] = v;
    }
    for (int i = t; i < MPTS; i += 256) dist[i] = 1e10f;
    if (t == 0) *s_cur = 0;
    __syncthreads();
    for (int it = 0; it < NP; ++it) {
        int cur = *s_cur;
        if (t < 3) {
            float v = xs[cur * 3 + t];
            cc[t] = v;
            agg[(n * NP + it) * 3 + t] = v;
        }
        __syncthreads();
        float bv = -1.0f; int bi = 0;
        float c0 = cc[0], c1 = cc[1], c2 = cc[2];
#pragma unroll
        for (int q = 0; q < 4; ++q) {
            int m = t * 4 + q;
            float dx = __fadd_rn(xs[m * 3 + 0], -c0);
            float dy = __fadd_rn(xs[m * 3 + 1], -c1);
            float dz = __fadd_rn(xs[m * 3 + 2], -c2);
            float d = __fadd_rn(__fadd_rn(__fmul_rn(dx, dx), __fmul_rn(dy, dy)), __fmul_rn(dz, dz));
            float dm = fminf(dist[m], d);
            dist[m] = dm;
            if (dm > bv) { bv = dm; bi = m; }
        }
        rv[t] = bv; ri[t] = bi;
        __syncthreads();
        if (t < 32) {
            float v = rv[t]; int idx = ri[t];
            for (int j = t + 32; j < 256; j += 32) {
                if (rv[j] > v) { v = rv[j]; idx = ri[j]; }
            }
#pragma unroll
            for (int off = 16; off; off >>= 1) {
                float ov = __shfl_down_sync(0xffffffffu, v, off);
                int   oi = __shfl_down_sync(0xffffffffu, idx, off);
                if (ov > v || (ov == v && oi < idx)) { v = ov; idx = oi; }
            }
            if (t == 0) *s_cur = idx;
        }
        __syncthreads();
    }
}

// ================= combo2: ballq (608 blocks) || ffgemm[152:304] =================
__global__ void combo2_kernel(const float* features, const float* agg) {
    extern __shared__ float cs[];
    int t = threadIdx.x;
    if (blockIdx.x >= 608) {
        ffgemm_part(features, cs, 152 + (blockIdx.x - 608), t);
        return;
    }
    int gw = (blockIdx.x * 256 + t) >> 5;
    int lane = t & 31;
    if (gw >= NB * NP) return;
    int n = gw >> 7, p = gw & 127;
    float cx = agg[(n * NP + p) * 3 + 0];
    float cy = agg[(n * NP + p) * 3 + 1];
    float cz = agg[(n * NP + p) * 3 + 2];
    const float* xb = g_x + n * MPTS * 3;
    int base = (n * NP + p) * NS;
    int cnt = 0, firstIdx = 0;
    bool haveFirst = false;
    for (int m0 = 0; m0 < MPTS; m0 += 32) {
        int m = m0 + lane;
        float dx = __fadd_rn(xb[m * 3 + 0], -cx);
        float dy = __fadd_rn(xb[m * 3 + 1], -cy);
        float dz = __fadd_rn(xb[m * 3 + 2], -cz);
        float d2 = __fadd_rn(__fadd_rn(__fmul_rn(dx, dx), __fmul_rn(dy, dy)), __fmul_rn(dz, dz));
        bool in = d2 < R2C;
        unsigned mask = __ballot_sync(0xffffffffu, in);
        if (!haveFirst && mask) { firstIdx = m0 + __ffs(mask) - 1; haveFirst = true; }
        int pr = __popc(mask & ((1u << lane) - 1u));
        if (in && cnt + pr < NS) g_idx[base + cnt + pr] = m;
        cnt += __popc(mask);
        if (cnt >= NS) break;
    }
    if (cnt > NS) cnt = NS;
    for (int j = cnt + lane; j < NS; j += 32) g_idx[base + j] = firstIdx;
}

// ================= tf32 128x128x128 GEMM (A [m][k], B [n][k], padded LDH) ============
__device__ __forceinline__ void gemm_tf32(float acc[2][8][4],
        const float* __restrict__ A, const float* __restrict__ B,
        int wm, int wn, int lane) {
    int ag = wm * 32 + (lane >> 2);
    int ak = lane & 3;
    int bg = wn * 64 + (lane >> 2);
#pragma unroll
    for (int kk = 0; kk < 16; ++kk) {
        int k0 = kk * 8 + ak;
        uint32_t a[2][4], b[8][2];
#pragma unroll
        for (int mt = 0; mt < 2; ++mt) {
            const float* ap = A + (ag + mt * 16) * LDH + k0;
            a[mt][0] = __float_as_uint(ap[0]);
            a[mt][1] = __float_as_uint(ap[8 * LDH]);
            a[mt][2] = __float_as_uint(ap[4]);
            a[mt][3] = __float_as_uint(ap[8 * LDH + 4]);
        }
#pragma unroll
        for (int nt = 0; nt < 8; ++nt) {
            const float* bp = B + (bg + nt * 8) * LDH + k0;
            b[nt][0] = __float_as_uint(bp[0]);
            b[nt][1] = __float_as_uint(bp[4]);
        }
#pragma unroll
        for (int mt = 0; mt < 2; ++mt)
#pragma unroll
            for (int nt = 0; nt < 8; ++nt)
                mma_tf32(acc[mt][nt], a[mt], b[nt]);
    }
}

// ================= fused persistent kernel =================
// smem floats: W2 @0 (128*LDH) | W3 @16896 | H @33792 | Wg @50688 (384)
//              beta @51072 | b2 @51200 | b3 @51328 | red @51456 (256) -> 51712 floats
#define FOFF_W3   16896
#define FOFF_H    33792
#define FOFF_WG   50688
#define FOFF_BETA 51072
#define FOFF_B2   51200
#define FOFF_B3   51328
#define FOFF_RED  51456
#define FUSED_SMEM_BYTES (51712 * 4)

__global__ void __launch_bounds__(256, 1) fused_kernel(const float* agg, float* featOut) {
    extern __shared__ float sm[];
    float* sW2   = sm;
    float* sW3   = sm + FOFF_W3;
    float* sH    = sm + FOFF_H;
    float* sWg   = sm + FOFF_WG;
    float* sBeta = sm + FOFF_BETA;
    float* sB2   = sm + FOFF_B2;
    float* sB3   = sm + FOFF_B3;
    float* sRed  = sm + FOFF_RED;

    int t = threadIdx.x;
    int warp = t >> 5, lane = t & 31;
    int wm = warp >> 1, wn = warp & 1;
    int row = t & 127;
    int half = t >> 7;
    int cbase = half * 64;

    // load weights + consts once
    {
        const float4* s2 = (const float4*)g_W2t;
        const float4* s3 = (const float4*)g_W3t;
        float4* d2 = (float4*)sW2;
        float4* d3 = (float4*)sW3;
        for (int i = t; i < 128 * LDH / 4; i += 256) { d2[i] = s2[i]; d3[i] = s3[i]; }
        for (int i = t; i < 384; i += 256) sWg[i] = g_Wg[i];
        if (t < 128) { sBeta[t] = g_beta1[t]; sB2[t] = g_bt2[t]; sB3[t] = g_bt3[t]; }
    }
    __syncthreads();

    for (int tile = blockIdx.x; tile < NTILE; tile += gridDim.x) {
        int n = tile >> 7, p = tile & 127;

        // ---- layer 1: gather FfT + xyz FMA + beta, relu, tf32-round, store H[s][c]
        {
            int s = row;
            int ix = g_idx[((n << 7) | p) * NS + s];
            float cx = agg[((n << 7) | p) * 3 + 0];
            float cy = agg[((n << 7) | p) * 3 + 1];
            float cz = agg[((n << 7) | p) * 3 + 2];
            const float* xp = g_x + (n * MPTS + ix) * 3;
            float g0 = (xp[0] - cx) / 0.15f;
            float g1 = (xp[1] - cy) / 0.15f;
            float g2 = (xp[2] - cz) / 0.15f;
            const float4* fb = (const float4*)(g_FfT + (((n << 10) + ix) << 7) + cbase);
            float* hrow = sH + s * LDH + cbase;
#pragma unroll
            for (int qq = 0; qq < 16; ++qq) {
                float4 a = fb[qq];
                float v0, v1, v2, v3;
                int c = cbase + qq * 4;
                v0 = tf32r(fmaxf(a.x + sWg[(c+0)*3]*g0 + sWg[(c+0)*3+1]*g1 + sWg[(c+0)*3+2]*g2 + sBeta[c+0], 0.0f));
                v1 = tf32r(fmaxf(a.y + sWg[(c+1)*3]*g0 + sWg[(c+1)*3+1]*g1 + sWg[(c+1)*3+2]*g2 + sBeta[c+1], 0.0f));
                v2 = tf32r(fmaxf(a.z + sWg[(c+2)*3]*g0 + sWg[(c+2)*3+1]*g1 + sWg[(c+2)*3+2]*g2 + sBeta[c+2], 0.0f));
                v3 = tf32r(fmaxf(a.w + sWg[(c+3)*3]*g0 + sWg[(c+3)*3+1]*g1 + sWg[(c+3)*3+2]*g2 + sBeta[c+3], 0.0f));
                float4 vv = {v0, v1, v2, v3};
                *(float4*)(hrow + qq * 4) = vv;
            }
        }
        __syncthreads();

        float acc[2][8][4];

        // ---- layer 2: D2[s][o2] = h1 @ W2^T
#pragma unroll
        for (int mt = 0; mt < 2; ++mt)
#pragma unroll
            for (int nt = 0; nt < 8; ++nt)
#pragma unroll
                for (int i = 0; i < 4; ++i) acc[mt][nt][i] = 0.0f;
        gemm_tf32(acc, sH, sW2, wm, wn, lane);
        __syncthreads();   // all h1 reads done before overwrite

        // epilogue: bias+relu+tf32, store h2 [s][o2]
#pragma unroll
        for (int mt = 0; mt < 2; ++mt) {
            int r0 = wm * 32 + mt * 16 + (lane >> 2);
#pragma unroll
            for (int nt = 0; nt < 8; ++nt) {
                int co = wn * 64 + nt * 8 + (lane & 3) * 2;
                float b0 = sB2[co], b1 = sB2[co + 1];
                float2 u0 = {tf32r(fmaxf(acc[mt][nt][0] + b0, 0.0f)),
                             tf32r(fmaxf(acc[mt][nt][1] + b1, 0.0f))};
                float2 u1 = {tf32r(fmaxf(acc[mt][nt][2] + b0, 0.0f)),
                             tf32r(fmaxf(acc[mt][nt][3] + b1, 0.0f))};
                *(float2*)(sH + r0 * LDH + co) = u0;
                *(float2*)(sH + (r0 + 8) * LDH + co) = u1;
            }
        }
        __syncthreads();

        // ---- layer 3: D3[o3][s] = W3 @ h2^T
#pragma unroll
        for (int mt = 0; mt < 2; ++mt)
#pragma unroll
            for (int nt = 0; nt < 8; ++nt)
#pragma unroll
                for (int i = 0; i < 4; ++i) acc[mt][nt][i] = 0.0f;
        gemm_tf32(acc, sW3, sH, wm, wn, lane);

        // reduce max over s (cols): in-register, quad shuffle, smem combine
#pragma unroll
        for (int mt = 0; mt < 2; ++mt) {
            float m0 = -1e30f, m1 = -1e30f;
#pragma unroll
            for (int nt = 0; nt < 8; ++nt) {
                m0 = fmaxf(m0, fmaxf(acc[mt][nt][0], acc[mt][nt][1]));
                m1 = fmaxf(m1, fmaxf(acc[mt][nt][2], acc[mt][nt][3]));
            }
            m0 = fmaxf(m0, __shfl_xor_sync(0xffffffffu, m0, 1));
            m0 = fmaxf(m0, __shfl_xor_sync(0xffffffffu, m0, 2));
            m1 = fmaxf(m1, __shfl_xor_sync(0xffffffffu, m1, 1));
            m1 = fmaxf(m1, __shfl_xor_sync(0xffffffffu, m1, 2));
            if ((lane & 3) == 0) {
                int r0 = wm * 32 + mt * 16 + (lane >> 2);
                sRed[r0 * 2 + wn] = m0;
                sRed[(r0 + 8) * 2 + wn] = m1;
            }
        }
        __syncthreads();
        if (t < 128) {
            float v = fmaxf(sRed[t * 2], sRed[t * 2 + 1]);
            featOut[(((n << 7) | t) << 7) | p] = fmaxf(v + sB3[t], 0.0f);
        }
        __syncthreads();
    }
}

// ================= fp32 128-GEMM helpers (head) =================
__device__ __forceinline__ void gemm128(const float* __restrict__ Wt, const float* hsm,
                                        float acc[8][8], int tx, int ty) {
#pragma unroll
    for (int j = 0; j < 8; ++j)
#pragma unroll
        for (int i = 0; i < 8; ++i) acc[j][i] = 0.0f;
#pragma unroll 4
    for (int c = 0; c < 128; ++c) {
        float4 w0 = *(const float4*)(Wt + c * 128 + ty * 8);
        float4 w1 = *(const float4*)(Wt + c * 128 + ty * 8 + 4);
        float4 h0 = *(const float4*)(hsm + c * 128 + tx * 8);
        float4 h1 = *(const float4*)(hsm + c * 128 + tx * 8 + 4);
        float wv[8] = {w0.x, w0.y, w0.z, w0.w, w1.x, w1.y, w1.z, w1.w};
        float hv[8] = {h0.x, h0.y, h0.z, h0.w, h1.x, h1.y, h1.z, h1.w};
#pragma unroll
        for (int j = 0; j < 8; ++j)
#pragma unroll
            for (int i = 0; i < 8; ++i) acc[j][i] += wv[j] * hv[i];
    }
}

__device__ __forceinline__ void relu_store(float* hsm, const float acc[8][8],
                                           const float* __restrict__ bias, int tx, int ty) {
#pragma unroll
    for (int j = 0; j < 8; ++j) {
        int o = ty * 8 + j;
        float bz = bias[o];
        float4 v0, v1;
        v0.x = fmaxf(acc[j][0] + bz, 0.0f); v0.y = fmaxf(acc[j][1] + bz, 0.0f);
        v0.z = fmaxf(acc[j][2] + bz, 0.0f); v0.w = fmaxf(acc[j][3] + bz, 0.0f);
        v1.x = fmaxf(acc[j][4] + bz, 0.0f); v1.y = fmaxf(acc[j][5] + bz, 0.0f);
        v1.z = fmaxf(acc[j][6] + bz, 0.0f); v1.w = fmaxf(acc[j][7] + bz, 0.0f);
        *(float4*)(hsm + o * 128 + tx * 8) = v0;
        *(float4*)(hsm + o * 128 + tx * 8 + 4) = v1;
    }
}

// ================= head =================
__global__ void head_kernel(const float* featIn, const float* agg,
                            const float* op_w, const float* op_b, float* scores) {
    extern __shared__ float A[];
    int n = blockIdx.x, t = threadIdx.x;
    for (int i = t; i < 16384; i += 256) A[i] = featIn[n * 16384 + i];
    __syncthreads();
    int tx = t & 15, ty = t >> 4;
    float acc[8][8];

    gemm128(g_Wc1, A, acc, tx, ty);
    __syncthreads();
    relu_store(A, acc, g_bc1, tx, ty);
    __syncthreads();

    gemm128(g_Wc2, A, acc, tx, ty);
    __syncthreads();
    relu_store(A, acc, g_bc2, tx, ty);
    __syncthreads();

    if (t < 128) {
        int p = t;
        int k = n % 19;
#pragma unroll
        for (int r = 0; r < 5; ++r) {
            float s = op_b[k * 5 + r];
            const float* wr = op_w + (k * 5 + r) * 128;
#pragma unroll 4
            for (int c = 0; c < 128; ++c) s += wr[c] * A[c * 128 + p];
            if (r >= 2) s += agg[(n * NP + p) * 3 + (r - 2)];
            scores[(n * NP + p) * 5 + r] = s;
        }
    }
}

// ================= launch =================
extern "C" void kernel_launch(void* const* d_in, const int* in_sizes, int n_in,
                              void* d_out, int out_size) {
    const float* xyz      = (const float*)d_in[0];
    const float* features = (const float*)d_in[1];
    const float* m1_w = (const float*)d_in[2];
    const float* m1_b = (const float*)d_in[3];
    const float* m1_g = (const float*)d_in[4];
    const float* m1_be = (const float*)d_in[5];
    const float* m2_w = (const float*)d_in[6];
    const float* m2_b = (const float*)d_in[7];
    const float* m2_g = (const float*)d_in[8];
    const float* m2_be = (const float*)d_in[9];
    const float* m3_w = (const float*)d_in[10];
    const float* m3_b = (const float*)d_in[11];
    const float* m3_g = (const float*)d_in[12];
    const float* m3_be = (const float*)d_in[13];
    const float* c1_w = (const float*)d_in[14];
    const float* c1_b = (const float*)d_in[15];
    const float* c1_g = (const float*)d_in[16];
    const float* c1_be = (const float*)d_in[17];
    const float* c2_w = (const float*)d_in[18];
    const float* c2_b = (const float*)d_in[19];
    const float* c2_g = (const float*)d_in[20];
    const float* c2_be = (const float*)d_in[21];
    const float* op_w = (const float*)d_in[22];
    const float* op_b = (const float*)d_in[23];

    float* out = (float*)d_out;
    float* scores = out;                       // 2*19*128*5
    float* agg    = out + 24320;               // 2*19*128*3
    float* feat   = out + 38912;               // 2*19*128*128

    prep_kernel<<<64, 256>>>(m1_w, m1_b, m1_g, m1_be, m2_w, m2_b, m2_g, m2_be,
                             m3_w, m3_b, m3_g, m3_be, c1_w, c1_b, c1_g, c1_be,
                             c2_w, c2_b, c2_g, c2_be);

    const int COMBO_SMEM = 4616 * 4;   // fps needs 4612 floats; ffgemm 4096
    combo1_kernel<<<NB + 152, 256, COMBO_SMEM>>>(xyz, features, agg);
    combo2_kernel<<<608 + 152, 256, COMBO_SMEM>>>(features, agg);

    cudaFuncSetAttribute(fused_kernel, cudaFuncAttributeMaxDynamicSharedMemorySize, FUSED_SMEM_BYTES);
    fused_kernel<<<148, 256, FUSED_SMEM_BYTES>>>(agg, feat);

    cudaFuncSetAttribute(head_kernel, cudaFuncAttributeMaxDynamicSharedMemorySize, 65536);
    head_kernel<<<NB, 256, 65536>>>(feat, agg, op_w, op_b, scores);
}